// round 6
// baseline (speedup 1.0000x reference)
#include <cuda_runtime.h>
#include <cuda_bf16.h>
#include <math.h>
#include <stdint.h>

// Problem dims (fixed): x [2,2048,2048] -> T=4096 tokens, H=2048, I=8192
#define T_TOK 4096
#define HDIM  2048
#define IDIM  8192
#define NGATE 16384   // 2*I rows in w_gate
#define PITCH 80      // padded smem row pitch (bytes) for 64B k-chunks

// ---------------- device scratch (static, allocation-free) ----------------
__device__ double      d_abssum[2];
__device__ float       d_wscale[2];
__device__ float       d_winv[2];
__device__ signed char d_wqg[(long long)NGATE * HDIM];   // ternary gate/up weights
__device__ signed char d_wqd[(long long)HDIM * IDIM];    // ternary down weights
__device__ signed char d_xq[(long long)T_TOK * HDIM];    // quantized activations L1
__device__ float       d_as1[T_TOK];
__device__ float       d_h[(long long)T_TOK * IDIM];     // SwiGLU output (fp32)
__device__ signed char d_hq[(long long)T_TOK * IDIM];    // quantized activations L2
__device__ float       d_as2[T_TOK];

// ---------------- PTX helpers (base PTX only: valid at sm_103 target) ------
__device__ __forceinline__ uint32_t smem_u32(const void* p) {
    return (uint32_t)__cvta_generic_to_shared(p);
}
__device__ __forceinline__ void cpa16(uint32_t s, const void* g) {
    asm volatile("cp.async.cg.shared.global [%0], [%1], 16;" :: "r"(s), "l"(g));
}
__device__ __forceinline__ void cp_commit() {
    asm volatile("cp.async.commit_group;");
}
__device__ __forceinline__ void ldsm4(uint32_t* r, uint32_t a) {
    asm volatile("ldmatrix.sync.aligned.m8n8.x4.shared.b16 {%0,%1,%2,%3}, [%4];"
        : "=r"(r[0]), "=r"(r[1]), "=r"(r[2]), "=r"(r[3]) : "r"(a));
}
__device__ __forceinline__ void mma_s8(int* c, const uint32_t* a, const uint32_t* b) {
    asm volatile(
        "mma.sync.aligned.m16n8k32.row.col.s32.s8.s8.s32 "
        "{%0,%1,%2,%3}, {%4,%5,%6,%7}, {%8,%9}, {%0,%1,%2,%3};"
        : "+r"(c[0]), "+r"(c[1]), "+r"(c[2]), "+r"(c[3])
        : "r"(a[0]), "r"(a[1]), "r"(a[2]), "r"(a[3]), "r"(b[0]), "r"(b[1]));
}
__device__ __forceinline__ float silu_mul(float g, float v) {
    return g / (1.f + expf(-g)) * v;
}

// ---------------- scalar pre-passes ----------------
__global__ void k_zero() { d_abssum[0] = 0.0; d_abssum[1] = 0.0; }

__global__ void k_abssum(const float* __restrict__ w, long long n, int slot) {
    float s = 0.f;
    long long stride = (long long)gridDim.x * blockDim.x;
    for (long long i = (long long)blockIdx.x * blockDim.x + threadIdx.x; i < n; i += stride)
        s += fabsf(w[i]);
    #pragma unroll
    for (int o = 16; o > 0; o >>= 1) s += __shfl_xor_sync(0xffffffffu, s, o);
    __shared__ double sb[8];
    int wid = threadIdx.x >> 5, lane = threadIdx.x & 31;
    if (lane == 0) sb[wid] = (double)s;
    __syncthreads();
    if (threadIdx.x == 0) {
        double t = 0.0;
        #pragma unroll
        for (int i = 0; i < 8; i++) t += sb[i];
        atomicAdd(&d_abssum[slot], t);
    }
}

__global__ void k_wscale() {
    float m0 = (float)(d_abssum[0] / (double)((long long)NGATE * HDIM));
    float m1 = (float)(d_abssum[1] / (double)((long long)HDIM * IDIM));
    float s0 = 1.f / fmaxf(m0, 1e-5f);
    float s1 = 1.f / fmaxf(m1, 1e-5f);
    d_wscale[0] = s0; d_wscale[1] = s1;
    d_winv[0] = 1.f / s0; d_winv[1] = 1.f / s1;
}

__global__ void k_wquant(const float4* __restrict__ w, long long n4, int which) {
    float s = d_wscale[which];
    signed char* q = which ? d_wqd : d_wqg;
    char4* q4 = reinterpret_cast<char4*>(q);
    long long stride = (long long)gridDim.x * blockDim.x;
    for (long long i = (long long)blockIdx.x * blockDim.x + threadIdx.x; i < n4; i += stride) {
        float4 v = w[i];
        char4 c;
        c.x = (signed char)fminf(fmaxf(rintf(v.x * s), -1.f), 1.f);
        c.y = (signed char)fminf(fmaxf(rintf(v.y * s), -1.f), 1.f);
        c.z = (signed char)fminf(fmaxf(rintf(v.z * s), -1.f), 1.f);
        c.w = (signed char)fminf(fmaxf(rintf(v.w * s), -1.f), 1.f);
        q4[i] = c;
    }
}

// ---------------- block reduction helper ----------------
__device__ __forceinline__ float block_reduce(float v, bool isMax) {
    __shared__ float sb[8];
    __syncthreads();
    #pragma unroll
    for (int o = 16; o > 0; o >>= 1) {
        float t = __shfl_xor_sync(0xffffffffu, v, o);
        v = isMax ? fmaxf(v, t) : (v + t);
    }
    int wid = threadIdx.x >> 5, lane = threadIdx.x & 31;
    if (lane == 0) sb[wid] = v;
    __syncthreads();
    float r;
    if (isMax) {
        r = fmaxf(fmaxf(fmaxf(sb[0], sb[1]), fmaxf(sb[2], sb[3])),
                  fmaxf(fmaxf(sb[4], sb[5]), fmaxf(sb[6], sb[7])));
    } else {
        r = sb[0] + sb[1] + sb[2] + sb[3] + sb[4] + sb[5] + sb[6] + sb[7];
    }
    return r;
}

// ---------------- RMSNorm + per-token int8 quantization ----------------
template <int HID, int VPT>
__global__ void __launch_bounds__(256) k_actquant(
    const float* __restrict__ x, const float* __restrict__ g,
    signed char* __restrict__ q, float* __restrict__ ascale)
{
    long long t = blockIdx.x;
    const float* xr = x + t * HID;
    float v[VPT];
    float ss = 0.f;
    #pragma unroll
    for (int j = 0; j < VPT; j++) {
        float f = xr[threadIdx.x + j * 256];
        v[j] = f;
        ss += f * f;
    }
    float var = block_reduce(ss, false) * (1.f / (float)HID);
    float r = rsqrtf(var + 1e-5f);
    float amax = 0.f;
    #pragma unroll
    for (int j = 0; j < VPT; j++) {
        float xn = v[j] * r * g[threadIdx.x + j * 256];
        v[j] = xn;
        amax = fmaxf(amax, fabsf(xn));
    }
    amax = block_reduce(amax, true);
    float s = 127.f / fmaxf(amax, 1e-5f);
    signed char* qr = q + t * HID;
    #pragma unroll
    for (int j = 0; j < VPT; j++) {
        float qf = fminf(fmaxf(rintf(v[j] * s), -128.f), 127.f);
        qr[threadIdx.x + j * 256] = (signed char)qf;
    }
    if (threadIdx.x == 0) ascale[t] = 1.f / s;
}

// ---------------- GEMM1 (IMMA): xq @ w_gate^T fused with SwiGLU -------------
// CTA: M=128 x N=128 (h cols); computes gate (rows nBase..) AND v (rows
// nBase+I..). 8 warps in 2(m) x 4(n); warp tile 64x32 per operand.
// smem per stage: A 128x80 + Bg 128x80 + Bv 128x80 = 30720B; 2 stages.
__global__ void __launch_bounds__(256, 1) k_gemm1() {
    extern __shared__ char smem[];
    const int tid = threadIdx.x;
    const int wid = tid >> 5, l = tid & 31;
    const int wm = wid >> 2, wn = wid & 3;
    const int mBase = blockIdx.y * 128;
    const int nBase = blockIdx.x * 128;
    const uint32_t sbase = smem_u32(smem);

    const signed char* Ag = d_xq  + (long long)mBase * HDIM;
    const signed char* Gg = d_wqg + (long long)nBase * HDIM;
    const signed char* Vg = d_wqg + (long long)(nBase + IDIM) * HDIM;

    int accg[4][4][4] = {};
    int accv[4][4][4] = {};

    // ldmatrix lane-address offsets (lane-dependent, stage-relative)
    const uint32_t aoff = (uint32_t)(wm * 64 + (l & 15)) * PITCH + (l >> 4) * 16;
    const uint32_t boff = (uint32_t)(wn * 32 + ((l >> 4) << 3) + (l & 7)) * PITCH
                        + ((l >> 3) & 1) * 16;

    // async loader for one 64B k-chunk into stage buf
    const int ltask0 = tid, row0 = ltask0 >> 2, seg0 = ltask0 & 3;
    const int ltask1 = tid + 256, row1 = ltask1 >> 2, seg1 = ltask1 & 3;

    #define G1_LOAD(buf, kt)                                                     \
    {                                                                            \
        uint32_t s0 = sbase + (buf) * 30720;                                     \
        long long g0 = (long long)row0 * HDIM + (kt) * 64 + seg0 * 16;           \
        uint32_t so0 = (uint32_t)row0 * PITCH + seg0 * 16;                       \
        cpa16(s0 + so0,          Ag + g0);                                       \
        cpa16(s0 + 10240 + so0,  Gg + g0);                                       \
        cpa16(s0 + 20480 + so0,  Vg + g0);                                       \
        long long g1 = (long long)row1 * HDIM + (kt) * 64 + seg1 * 16;           \
        uint32_t so1 = (uint32_t)row1 * PITCH + seg1 * 16;                       \
        cpa16(s0 + so1,          Ag + g1);                                       \
        cpa16(s0 + 10240 + so1,  Gg + g1);                                       \
        cpa16(s0 + 20480 + so1,  Vg + g1);                                       \
        cp_commit();                                                             \
    }

    G1_LOAD(0, 0);

    const int NK = HDIM / 64;  // 32
    for (int kt = 0; kt < NK; kt++) {
        const int buf = kt & 1;
        if (kt + 1 < NK) {
            G1_LOAD(buf ^ 1, kt + 1);
            asm volatile("cp.async.wait_group 1;");
        } else {
            asm volatile("cp.async.wait_group 0;");
        }
        __syncthreads();
        const uint32_t As = sbase + buf * 30720;
        const uint32_t Bg = As + 10240, Bv = As + 20480;
        #pragma unroll
        for (int ks = 0; ks < 2; ks++) {
            uint32_t a[4][4];
            #pragma unroll
            for (int mf = 0; mf < 4; mf++)
                ldsm4(a[mf], As + aoff + mf * (16 * PITCH) + ks * 32);
            uint32_t bg[2][4], bv[2][4];
            #pragma unroll
            for (int p = 0; p < 2; p++) {
                ldsm4(bg[p], Bg + boff + p * (16 * PITCH) + ks * 32);
                ldsm4(bv[p], Bv + boff + p * (16 * PITCH) + ks * 32);
            }
            #pragma unroll
            for (int mf = 0; mf < 4; mf++) {
                #pragma unroll
                for (int nf = 0; nf < 4; nf++) {
                    mma_s8(accg[mf][nf], a[mf], &bg[nf >> 1][(nf & 1) * 2]);
                    mma_s8(accv[mf][nf], a[mf], &bv[nf >> 1][(nf & 1) * 2]);
                }
            }
        }
        __syncthreads();
    }
    #undef G1_LOAD

    // epilogue: dequant + SwiGLU -> d_h (fp32)
    const float wiv = d_winv[0];
    #pragma unroll
    for (int mf = 0; mf < 4; mf++) {
        const int r0 = mBase + wm * 64 + mf * 16 + (l >> 2);
        const float s0 = d_as1[r0] * wiv;
        const float s1 = d_as1[r0 + 8] * wiv;
        float* h0 = d_h + (long long)r0 * IDIM;
        float* h1 = d_h + (long long)(r0 + 8) * IDIM;
        #pragma unroll
        for (int nf = 0; nf < 4; nf++) {
            const int c0 = nBase + wn * 32 + nf * 8 + (l & 3) * 2;
            float2 o0, o1;
            o0.x = silu_mul((float)accg[mf][nf][0] * s0, (float)accv[mf][nf][0] * s0);
            o0.y = silu_mul((float)accg[mf][nf][1] * s0, (float)accv[mf][nf][1] * s0);
            o1.x = silu_mul((float)accg[mf][nf][2] * s1, (float)accv[mf][nf][2] * s1);
            o1.y = silu_mul((float)accg[mf][nf][3] * s1, (float)accv[mf][nf][3] * s1);
            *(float2*)(h0 + c0) = o0;
            *(float2*)(h1 + c0) = o1;
        }
    }
}

// ---------------- GEMM2 (IMMA): hq @ w_down^T -> fp32 out -------------------
// CTA: M=128 x N=128, K=8192. smem per stage: A + B = 20480B; 2 stages.
__global__ void __launch_bounds__(256, 2) k_gemm2(float* __restrict__ out) {
    extern __shared__ char smem[];
    const int tid = threadIdx.x;
    const int wid = tid >> 5, l = tid & 31;
    const int wm = wid >> 2, wn = wid & 3;
    const int mBase = blockIdx.y * 128;
    const int nBase = blockIdx.x * 128;
    const uint32_t sbase = smem_u32(smem);

    const signed char* Ag = d_hq  + (long long)mBase * IDIM;
    const signed char* Wg = d_wqd + (long long)nBase * IDIM;

    int acc[4][4][4] = {};

    const uint32_t aoff = (uint32_t)(wm * 64 + (l & 15)) * PITCH + (l >> 4) * 16;
    const uint32_t boff = (uint32_t)(wn * 32 + ((l >> 4) << 3) + (l & 7)) * PITCH
                        + ((l >> 3) & 1) * 16;

    const int ltask0 = tid, row0 = ltask0 >> 2, seg0 = ltask0 & 3;
    const int ltask1 = tid + 256, row1 = ltask1 >> 2, seg1 = ltask1 & 3;

    #define G2_LOAD(buf, kt)                                                     \
    {                                                                            \
        uint32_t s0 = sbase + (buf) * 20480;                                     \
        long long g0 = (long long)row0 * IDIM + (kt) * 64 + seg0 * 16;           \
        uint32_t so0 = (uint32_t)row0 * PITCH + seg0 * 16;                       \
        cpa16(s0 + so0,         Ag + g0);                                        \
        cpa16(s0 + 10240 + so0, Wg + g0);                                        \
        long long g1 = (long long)row1 * IDIM + (kt) * 64 + seg1 * 16;           \
        uint32_t so1 = (uint32_t)row1 * PITCH + seg1 * 16;                       \
        cpa16(s0 + so1,         Ag + g1);                                        \
        cpa16(s0 + 10240 + so1, Wg + g1);                                        \
        cp_commit();                                                             \
    }

    G2_LOAD(0, 0);

    const int NK = IDIM / 64;  // 128
    for (int kt = 0; kt < NK; kt++) {
        const int buf = kt & 1;
        if (kt + 1 < NK) {
            G2_LOAD(buf ^ 1, kt + 1);
            asm volatile("cp.async.wait_group 1;");
        } else {
            asm volatile("cp.async.wait_group 0;");
        }
        __syncthreads();
        const uint32_t As = sbase + buf * 20480;
        const uint32_t Bs = As + 10240;
        #pragma unroll
        for (int ks = 0; ks < 2; ks++) {
            uint32_t a[4][4];
            #pragma unroll
            for (int mf = 0; mf < 4; mf++)
                ldsm4(a[mf], As + aoff + mf * (16 * PITCH) + ks * 32);
            uint32_t b[2][4];
            #pragma unroll
            for (int p = 0; p < 2; p++)
                ldsm4(b[p], Bs + boff + p * (16 * PITCH) + ks * 32);
            #pragma unroll
            for (int mf = 0; mf < 4; mf++) {
                #pragma unroll
                for (int nf = 0; nf < 4; nf++)
                    mma_s8(acc[mf][nf], a[mf], &b[nf >> 1][(nf & 1) * 2]);
            }
        }
        __syncthreads();
    }
    #undef G2_LOAD

    const float wiv = d_winv[1];
    #pragma unroll
    for (int mf = 0; mf < 4; mf++) {
        const int r0 = mBase + wm * 64 + mf * 16 + (l >> 2);
        const float s0 = d_as2[r0] * wiv;
        const float s1 = d_as2[r0 + 8] * wiv;
        float* o0p = out + (long long)r0 * HDIM;
        float* o1p = out + (long long)(r0 + 8) * HDIM;
        #pragma unroll
        for (int nf = 0; nf < 4; nf++) {
            const int c0 = nBase + wn * 32 + nf * 8 + (l & 3) * 2;
            float2 o0, o1;
            o0.x = (float)acc[mf][nf][0] * s0;
            o0.y = (float)acc[mf][nf][1] * s0;
            o1.x = (float)acc[mf][nf][2] * s1;
            o1.y = (float)acc[mf][nf][3] * s1;
            *(float2*)(o0p + c0) = o0;
            *(float2*)(o1p + c0) = o1;
        }
    }
}

// ---------------- host ----------------
extern "C" void kernel_launch(void* const* d_in, const int* in_sizes, int n_in,
                              void* d_out, int out_size) {
    const float* x      = (const float*)d_in[0];
    const float* w_gate = (const float*)d_in[1];
    const float* g_gate = (const float*)d_in[2];
    const float* w_down = (const float*)d_in[3];
    const float* g_down = (const float*)d_in[4];
    float* out = (float*)d_out;

    signed char* p_xq = nullptr; float* p_as1 = nullptr;
    float* p_h = nullptr; signed char* p_hq = nullptr; float* p_as2 = nullptr;
    cudaGetSymbolAddress((void**)&p_xq,  d_xq);
    cudaGetSymbolAddress((void**)&p_as1, d_as1);
    cudaGetSymbolAddress((void**)&p_h,   d_h);
    cudaGetSymbolAddress((void**)&p_hq,  d_hq);
    cudaGetSymbolAddress((void**)&p_as2, d_as2);

    const int SM1 = 61440;   // 2 stages x 30720
    const int SM2 = 40960;   // 2 stages x 20480
    cudaFuncSetAttribute(k_gemm1, cudaFuncAttributeMaxDynamicSharedMemorySize, SM1);
    cudaFuncSetAttribute(k_gemm2, cudaFuncAttributeMaxDynamicSharedMemorySize, SM2);

    // 1) weight scales
    k_zero<<<1, 1>>>();
    k_abssum<<<2048, 256>>>(w_gate, (long long)NGATE * HDIM, 0);
    k_abssum<<<1024, 256>>>(w_down, (long long)HDIM * IDIM, 1);
    k_wscale<<<1, 1>>>();

    // 2) ternarize weights -> s8
    k_wquant<<<4096, 256>>>((const float4*)w_gate, (long long)NGATE * HDIM / 4, 0);
    k_wquant<<<2048, 256>>>((const float4*)w_down, (long long)HDIM * IDIM / 4, 1);

    // 3) RMSNorm + quantize x -> s8
    k_actquant<HDIM, HDIM / 256><<<T_TOK, 256>>>(x, g_gate, p_xq, p_as1);

    // 4) GEMM1 + SwiGLU -> h (fp32)
    k_gemm1<<<dim3(IDIM / 128, T_TOK / 128), 256, SM1>>>();

    // 5) RMSNorm + quantize h -> s8
    k_actquant<IDIM, IDIM / 256><<<T_TOK, 256>>>(p_h, g_down, p_hq, p_as2);

    // 6) GEMM2 -> out
    k_gemm2<<<dim3(HDIM / 128, T_TOK / 128), 256, SM2>>>(out);
}

// round 7
// speedup vs baseline: 1.9203x; 1.9203x over previous
#include <cuda_runtime.h>
#include <cuda_bf16.h>
#include <math.h>
#include <stdint.h>

// Problem dims (fixed): x [2,2048,2048] -> T=4096 tokens, H=2048, I=8192
#define T_TOK 4096
#define HDIM  2048
#define IDIM  8192
#define NGATE 16384   // 2*I rows in w_gate
#define PITCH 80      // padded smem row pitch (bytes) for 64B k-chunks

// ---------------- device scratch (static, allocation-free) ----------------
__device__ double        d_abssum[2];
__device__ float         d_wscale[2];
__device__ float         d_winv[2];
__device__ __nv_bfloat16 d_wqg[(long long)NGATE * HDIM];  // ternary gate/up weights
__device__ __nv_bfloat16 d_wqd[(long long)HDIM * IDIM];   // ternary down weights
__device__ __nv_bfloat16 d_xq[(long long)T_TOK * HDIM];   // quantized activations L1
__device__ float         d_as1[T_TOK];
__device__ float         d_h[(long long)T_TOK * IDIM];    // SwiGLU output (fp32)
__device__ __nv_bfloat16 d_hq[(long long)T_TOK * IDIM];   // quantized activations L2
__device__ float         d_as2[T_TOK];

// ---------------- PTX helpers (base PTX only: valid at sm_103 target) ------
__device__ __forceinline__ uint32_t smem_u32(const void* p) {
    return (uint32_t)__cvta_generic_to_shared(p);
}
__device__ __forceinline__ void cpa16(uint32_t s, const void* g) {
    asm volatile("cp.async.cg.shared.global [%0], [%1], 16;" :: "r"(s), "l"(g));
}
__device__ __forceinline__ void cp_commit() {
    asm volatile("cp.async.commit_group;");
}
__device__ __forceinline__ void ldsm4(uint32_t* r, uint32_t a) {
    asm volatile("ldmatrix.sync.aligned.m8n8.x4.shared.b16 {%0,%1,%2,%3}, [%4];"
        : "=r"(r[0]), "=r"(r[1]), "=r"(r[2]), "=r"(r[3]) : "r"(a));
}
// bf16 HMMA: D(f32) = A(bf16) @ B(bf16) + D, m16n8k16
__device__ __forceinline__ void mma_bf16(float* c, const uint32_t* a, const uint32_t* b) {
    asm volatile(
        "mma.sync.aligned.m16n8k16.row.col.f32.bf16.bf16.f32 "
        "{%0,%1,%2,%3}, {%4,%5,%6,%7}, {%8,%9}, {%0,%1,%2,%3};"
        : "+f"(c[0]), "+f"(c[1]), "+f"(c[2]), "+f"(c[3])
        : "r"(a[0]), "r"(a[1]), "r"(a[2]), "r"(a[3]), "r"(b[0]), "r"(b[1]));
}
__device__ __forceinline__ float silu_mul(float g, float v) {
    return g / (1.f + expf(-g)) * v;
}

// ---------------- scalar pre-passes ----------------
__global__ void k_zero() { d_abssum[0] = 0.0; d_abssum[1] = 0.0; }

__global__ void k_abssum(const float* __restrict__ w, long long n, int slot) {
    float s = 0.f;
    long long stride = (long long)gridDim.x * blockDim.x;
    for (long long i = (long long)blockIdx.x * blockDim.x + threadIdx.x; i < n; i += stride)
        s += fabsf(w[i]);
    #pragma unroll
    for (int o = 16; o > 0; o >>= 1) s += __shfl_xor_sync(0xffffffffu, s, o);
    __shared__ double sb[8];
    int wid = threadIdx.x >> 5, lane = threadIdx.x & 31;
    if (lane == 0) sb[wid] = (double)s;
    __syncthreads();
    if (threadIdx.x == 0) {
        double t = 0.0;
        #pragma unroll
        for (int i = 0; i < 8; i++) t += sb[i];
        atomicAdd(&d_abssum[slot], t);
    }
}

__global__ void k_wscale() {
    float m0 = (float)(d_abssum[0] / (double)((long long)NGATE * HDIM));
    float m1 = (float)(d_abssum[1] / (double)((long long)HDIM * IDIM));
    float s0 = 1.f / fmaxf(m0, 1e-5f);
    float s1 = 1.f / fmaxf(m1, 1e-5f);
    d_wscale[0] = s0; d_wscale[1] = s1;
    d_winv[0] = 1.f / s0; d_winv[1] = 1.f / s1;
}

// ternarize: clip(round(w*s), -1, 1) -> bf16 (exact small ints)
__global__ void k_wquant(const float4* __restrict__ w, long long n4, int which) {
    float s = d_wscale[which];
    __nv_bfloat162* q2 = reinterpret_cast<__nv_bfloat162*>(which ? d_wqd : d_wqg);
    long long stride = (long long)gridDim.x * blockDim.x;
    for (long long i = (long long)blockIdx.x * blockDim.x + threadIdx.x; i < n4; i += stride) {
        float4 v = w[i];
        float a = fminf(fmaxf(rintf(v.x * s), -1.f), 1.f);
        float b = fminf(fmaxf(rintf(v.y * s), -1.f), 1.f);
        float c = fminf(fmaxf(rintf(v.z * s), -1.f), 1.f);
        float d = fminf(fmaxf(rintf(v.w * s), -1.f), 1.f);
        q2[i * 2 + 0] = __floats2bfloat162_rn(a, b);
        q2[i * 2 + 1] = __floats2bfloat162_rn(c, d);
    }
}

// ---------------- block reduction helper ----------------
__device__ __forceinline__ float block_reduce(float v, bool isMax) {
    __shared__ float sb[8];
    __syncthreads();
    #pragma unroll
    for (int o = 16; o > 0; o >>= 1) {
        float t = __shfl_xor_sync(0xffffffffu, v, o);
        v = isMax ? fmaxf(v, t) : (v + t);
    }
    int wid = threadIdx.x >> 5, lane = threadIdx.x & 31;
    if (lane == 0) sb[wid] = v;
    __syncthreads();
    float r;
    if (isMax) {
        r = fmaxf(fmaxf(fmaxf(sb[0], sb[1]), fmaxf(sb[2], sb[3])),
                  fmaxf(fmaxf(sb[4], sb[5]), fmaxf(sb[6], sb[7])));
    } else {
        r = sb[0] + sb[1] + sb[2] + sb[3] + sb[4] + sb[5] + sb[6] + sb[7];
    }
    return r;
}

// ---------------- RMSNorm + per-token int8 quant (stored as bf16 ints) -----
template <int HID, int VPT>
__global__ void __launch_bounds__(256) k_actquant(
    const float* __restrict__ x, const float* __restrict__ g,
    __nv_bfloat16* __restrict__ q, float* __restrict__ ascale)
{
    long long t = blockIdx.x;
    const float* xr = x + t * HID;
    float v[VPT];
    float ss = 0.f;
    #pragma unroll
    for (int j = 0; j < VPT; j++) {
        float f = xr[threadIdx.x + j * 256];
        v[j] = f;
        ss += f * f;
    }
    float var = block_reduce(ss, false) * (1.f / (float)HID);
    float r = rsqrtf(var + 1e-5f);
    float amax = 0.f;
    #pragma unroll
    for (int j = 0; j < VPT; j++) {
        float xn = v[j] * r * g[threadIdx.x + j * 256];
        v[j] = xn;
        amax = fmaxf(amax, fabsf(xn));
    }
    amax = block_reduce(amax, true);
    float s = 127.f / fmaxf(amax, 1e-5f);
    __nv_bfloat16* qr = q + t * HID;
    #pragma unroll
    for (int j = 0; j < VPT; j++) {
        float qf = fminf(fmaxf(rintf(v[j] * s), -128.f), 127.f);
        qr[threadIdx.x + j * 256] = __float2bfloat16(qf);  // exact (|int| <= 128)
    }
    if (threadIdx.x == 0) ascale[t] = 1.f / s;
}

// ---------------- GEMM1 (HMMA bf16): xq @ w_gate^T fused with SwiGLU -------
// CTA: M=128 x N=128 (h cols); computes gate (rows nBase..) AND v (rows
// nBase+I..). 8 warps in 2(m) x 4(n); warp tile 64x32 per operand.
// k-chunk = 32 bf16 = 64B/row; smem per stage: 3 x (128 x 80B) = 30720B; x2.
__global__ void __launch_bounds__(256, 1) k_gemm1() {
    extern __shared__ char smem[];
    const int tid = threadIdx.x;
    const int wid = tid >> 5, l = tid & 31;
    const int wm = wid >> 2, wn = wid & 3;
    const int mBase = blockIdx.y * 128;
    const int nBase = blockIdx.x * 128;
    const uint32_t sbase = smem_u32(smem);

    const char* Ag = (const char*)d_xq  + (long long)mBase * HDIM * 2;
    const char* Gg = (const char*)d_wqg + (long long)nBase * HDIM * 2;
    const char* Vg = (const char*)d_wqg + (long long)(nBase + IDIM) * HDIM * 2;

    float accg[4][4][4] = {};
    float accv[4][4][4] = {};

    // ldmatrix lane-address offsets (stage-relative)
    const uint32_t aoff = (uint32_t)(wm * 64 + (l & 15)) * PITCH + (l >> 4) * 16;
    const uint32_t boff = (uint32_t)(wn * 32 + ((l >> 4) << 3) + (l & 7)) * PITCH
                        + ((l >> 3) & 1) * 16;

    const int row0 = tid >> 2,        seg0 = tid & 3;
    const int row1 = (tid + 256) >> 2, seg1 = tid & 3;  // +256: row += 64, same seg

    #define G1_LOAD(buf, kt)                                                     \
    {                                                                            \
        uint32_t s0 = sbase + (buf) * 30720;                                     \
        long long g0 = (long long)row0 * (HDIM * 2) + (kt) * 64 + seg0 * 16;     \
        uint32_t so0 = (uint32_t)row0 * PITCH + seg0 * 16;                       \
        cpa16(s0 + so0,          Ag + g0);                                       \
        cpa16(s0 + 10240 + so0,  Gg + g0);                                       \
        cpa16(s0 + 20480 + so0,  Vg + g0);                                       \
        long long g1 = (long long)row1 * (HDIM * 2) + (kt) * 64 + seg1 * 16;     \
        uint32_t so1 = (uint32_t)row1 * PITCH + seg1 * 16;                       \
        cpa16(s0 + so1,          Ag + g1);                                       \
        cpa16(s0 + 10240 + so1,  Gg + g1);                                       \
        cpa16(s0 + 20480 + so1,  Vg + g1);                                       \
        cp_commit();                                                             \
    }

    G1_LOAD(0, 0);

    const int NK = HDIM / 32;  // 64 chunks of 32 bf16 (64B)
    for (int kt = 0; kt < NK; kt++) {
        const int buf = kt & 1;
        if (kt + 1 < NK) {
            G1_LOAD(buf ^ 1, kt + 1);
            asm volatile("cp.async.wait_group 1;");
        } else {
            asm volatile("cp.async.wait_group 0;");
        }
        __syncthreads();
        const uint32_t As = sbase + buf * 30720;
        const uint32_t Bg = As + 10240, Bv = As + 20480;
        #pragma unroll
        for (int ks = 0; ks < 2; ks++) {     // two K=16 groups per 64B chunk
            uint32_t a[4][4];
            #pragma unroll
            for (int mf = 0; mf < 4; mf++)
                ldsm4(a[mf], As + aoff + mf * (16 * PITCH) + ks * 32);
            uint32_t bg[2][4], bv[2][4];
            #pragma unroll
            for (int p = 0; p < 2; p++) {
                ldsm4(bg[p], Bg + boff + p * (16 * PITCH) + ks * 32);
                ldsm4(bv[p], Bv + boff + p * (16 * PITCH) + ks * 32);
            }
            #pragma unroll
            for (int mf = 0; mf < 4; mf++) {
                #pragma unroll
                for (int nf = 0; nf < 4; nf++) {
                    mma_bf16(accg[mf][nf], a[mf], &bg[nf >> 1][(nf & 1) * 2]);
                    mma_bf16(accv[mf][nf], a[mf], &bv[nf >> 1][(nf & 1) * 2]);
                }
            }
        }
        __syncthreads();
    }
    #undef G1_LOAD

    // epilogue: dequant + SwiGLU -> d_h (fp32)
    const float wiv = d_winv[0];
    #pragma unroll
    for (int mf = 0; mf < 4; mf++) {
        const int r0 = mBase + wm * 64 + mf * 16 + (l >> 2);
        const float s0 = d_as1[r0] * wiv;
        const float s1 = d_as1[r0 + 8] * wiv;
        float* h0 = d_h + (long long)r0 * IDIM;
        float* h1 = d_h + (long long)(r0 + 8) * IDIM;
        #pragma unroll
        for (int nf = 0; nf < 4; nf++) {
            const int c0 = nBase + wn * 32 + nf * 8 + (l & 3) * 2;
            float2 o0, o1;
            o0.x = silu_mul(accg[mf][nf][0] * s0, accv[mf][nf][0] * s0);
            o0.y = silu_mul(accg[mf][nf][1] * s0, accv[mf][nf][1] * s0);
            o1.x = silu_mul(accg[mf][nf][2] * s1, accv[mf][nf][2] * s1);
            o1.y = silu_mul(accg[mf][nf][3] * s1, accv[mf][nf][3] * s1);
            *(float2*)(h0 + c0) = o0;
            *(float2*)(h1 + c0) = o1;
        }
    }
}

// ---------------- GEMM2 (HMMA bf16): hq @ w_down^T -> fp32 out --------------
__global__ void __launch_bounds__(256, 1) k_gemm2(float* __restrict__ out) {
    extern __shared__ char smem[];
    const int tid = threadIdx.x;
    const int wid = tid >> 5, l = tid & 31;
    const int wm = wid >> 2, wn = wid & 3;
    const int mBase = blockIdx.y * 128;
    const int nBase = blockIdx.x * 128;
    const uint32_t sbase = smem_u32(smem);

    const char* Ag = (const char*)d_hq  + (long long)mBase * IDIM * 2;
    const char* Wg = (const char*)d_wqd + (long long)nBase * IDIM * 2;

    float acc[4][4][4] = {};

    const uint32_t aoff = (uint32_t)(wm * 64 + (l & 15)) * PITCH + (l >> 4) * 16;
    const uint32_t boff = (uint32_t)(wn * 32 + ((l >> 4) << 3) + (l & 7)) * PITCH
                        + ((l >> 3) & 1) * 16;

    const int row0 = tid >> 2,         seg0 = tid & 3;
    const int row1 = (tid + 256) >> 2, seg1 = tid & 3;

    #define G2_LOAD(buf, kt)                                                     \
    {                                                                            \
        uint32_t s0 = sbase + (buf) * 20480;                                     \
        long long g0 = (long long)row0 * (IDIM * 2) + (kt) * 64 + seg0 * 16;     \
        uint32_t so0 = (uint32_t)row0 * PITCH + seg0 * 16;                       \
        cpa16(s0 + so0,         Ag + g0);                                        \
        cpa16(s0 + 10240 + so0, Wg + g0);                                        \
        long long g1 = (long long)row1 * (IDIM * 2) + (kt) * 64 + seg1 * 16;     \
        uint32_t so1 = (uint32_t)row1 * PITCH + seg1 * 16;                       \
        cpa16(s0 + so1,         Ag + g1);                                        \
        cpa16(s0 + 10240 + so1, Wg + g1);                                        \
        cp_commit();                                                             \
    }

    G2_LOAD(0, 0);

    const int NK = IDIM / 32;  // 256 chunks
    for (int kt = 0; kt < NK; kt++) {
        const int buf = kt & 1;
        if (kt + 1 < NK) {
            G2_LOAD(buf ^ 1, kt + 1);
            asm volatile("cp.async.wait_group 1;");
        } else {
            asm volatile("cp.async.wait_group 0;");
        }
        __syncthreads();
        const uint32_t As = sbase + buf * 20480;
        const uint32_t Bs = As + 10240;
        #pragma unroll
        for (int ks = 0; ks < 2; ks++) {
            uint32_t a[4][4];
            #pragma unroll
            for (int mf = 0; mf < 4; mf++)
                ldsm4(a[mf], As + aoff + mf * (16 * PITCH) + ks * 32);
            uint32_t b[2][4];
            #pragma unroll
            for (int p = 0; p < 2; p++)
                ldsm4(b[p], Bs + boff + p * (16 * PITCH) + ks * 32);
            #pragma unroll
            for (int mf = 0; mf < 4; mf++) {
                #pragma unroll
                for (int nf = 0; nf < 4; nf++)
                    mma_bf16(acc[mf][nf], a[mf], &b[nf >> 1][(nf & 1) * 2]);
            }
        }
        __syncthreads();
    }
    #undef G2_LOAD

    const float wiv = d_winv[1];
    #pragma unroll
    for (int mf = 0; mf < 4; mf++) {
        const int r0 = mBase + wm * 64 + mf * 16 + (l >> 2);
        const float s0 = d_as2[r0] * wiv;
        const float s1 = d_as2[r0 + 8] * wiv;
        float* o0p = out + (long long)r0 * HDIM;
        float* o1p = out + (long long)(r0 + 8) * HDIM;
        #pragma unroll
        for (int nf = 0; nf < 4; nf++) {
            const int c0 = nBase + wn * 32 + nf * 8 + (l & 3) * 2;
            float2 o0, o1;
            o0.x = acc[mf][nf][0] * s0;
            o0.y = acc[mf][nf][1] * s0;
            o1.x = acc[mf][nf][2] * s1;
            o1.y = acc[mf][nf][3] * s1;
            *(float2*)(o0p + c0) = o0;
            *(float2*)(o1p + c0) = o1;
        }
    }
}

// ---------------- host ----------------
extern "C" void kernel_launch(void* const* d_in, const int* in_sizes, int n_in,
                              void* d_out, int out_size) {
    const float* x      = (const float*)d_in[0];
    const float* w_gate = (const float*)d_in[1];
    const float* g_gate = (const float*)d_in[2];
    const float* w_down = (const float*)d_in[3];
    const float* g_down = (const float*)d_in[4];
    float* out = (float*)d_out;

    __nv_bfloat16* p_xq = nullptr; float* p_as1 = nullptr;
    float* p_h = nullptr; __nv_bfloat16* p_hq = nullptr; float* p_as2 = nullptr;
    cudaGetSymbolAddress((void**)&p_xq,  d_xq);
    cudaGetSymbolAddress((void**)&p_as1, d_as1);
    cudaGetSymbolAddress((void**)&p_h,   d_h);
    cudaGetSymbolAddress((void**)&p_hq,  d_hq);
    cudaGetSymbolAddress((void**)&p_as2, d_as2);

    const int SM1 = 61440;   // 2 stages x 30720
    const int SM2 = 40960;   // 2 stages x 20480
    cudaFuncSetAttribute(k_gemm1, cudaFuncAttributeMaxDynamicSharedMemorySize, SM1);
    cudaFuncSetAttribute(k_gemm2, cudaFuncAttributeMaxDynamicSharedMemorySize, SM2);

    // 1) weight scales
    k_zero<<<1, 1>>>();
    k_abssum<<<2048, 256>>>(w_gate, (long long)NGATE * HDIM, 0);
    k_abssum<<<1024, 256>>>(w_down, (long long)HDIM * IDIM, 1);
    k_wscale<<<1, 1>>>();

    // 2) ternarize weights -> bf16
    k_wquant<<<4096, 256>>>((const float4*)w_gate, (long long)NGATE * HDIM / 4, 0);
    k_wquant<<<2048, 256>>>((const float4*)w_down, (long long)HDIM * IDIM / 4, 1);

    // 3) RMSNorm + quantize x -> bf16 ints
    k_actquant<HDIM, HDIM / 256><<<T_TOK, 256>>>(x, g_gate, p_xq, p_as1);

    // 4) GEMM1 + SwiGLU -> h (fp32)
    k_gemm1<<<dim3(IDIM / 128, T_TOK / 128), 256, SM1>>>();

    // 5) RMSNorm + quantize h -> bf16 ints
    k_actquant<IDIM, IDIM / 256><<<T_TOK, 256>>>(p_h, g_down, p_hq, p_as2);

    // 6) GEMM2 -> out
    k_gemm2<<<dim3(HDIM / 128, T_TOK / 128), 256, SM2>>>(out);
}